// round 1
// baseline (speedup 1.0000x reference)
#include <cuda_runtime.h>
#include <cstdint>

// ---------------- problem constants ----------------
#define DD   44          // DESIZE
#define HH   48
#define WW   48
#define DHW  (DD*HH*WW)  // 101376 = FLAT
#define NB   4           // batch
#define N1   1024
#define N2   128
#define N3   10
#define CONVEY 0.9f

// ---------------- device scratch (no allocation allowed) ----------------
__device__ float4 g_neuA[DHW];   // batch-packed neuron state, ping
__device__ float4 g_neuB[DHW];   // pong
__device__ float  g_acc1[NB * N1];
__device__ float  g_acc2[NB * N2];

// ---------------- packed fp32x2 helpers (Blackwell) ----------------
__device__ __forceinline__ unsigned long long pack2(float w) {
    unsigned long long r;
    asm("mov.b64 %0, {%1, %1};" : "=l"(r) : "f"(w));
    return r;
}
__device__ __forceinline__ void ffma2(unsigned long long& acc,
                                      unsigned long long a,
                                      unsigned long long b) {
    asm("fma.rn.f32x2 %0, %1, %2, %0;" : "+l"(acc) : "l"(a), "l"(b));
}
__device__ __forceinline__ float2 unpack2(unsigned long long v) {
    float2 f;
    asm("mov.b64 {%0, %1}, %2;" : "=f"(f.x), "=f"(f.y) : "l"(v));
    return f;
}

// ---------------- kernel 1: neu = vinput + frame, batch-packed ----------------
__global__ void __launch_bounds__(256) k_init_neu(const float* __restrict__ vin,
                                                  const float* __restrict__ frame) {
    int v = blockIdx.x * 256 + threadIdx.x;
    if (v >= DHW) return;
    float f = frame[v];
    float4 o;
    o.x = vin[0 * DHW + v] + f;
    o.y = vin[1 * DHW + v] + f;
    o.z = vin[2 * DHW + v] + f;
    o.w = vin[3 * DHW + v] + f;
    g_neuA[v] = o;
}

// ---------------- kernel 2: one locally-connected step ----------------
// dir = 0: A -> B, dir = 1: B -> A
__global__ void __launch_bounds__(256) k_step(const float4* __restrict__ syn4, int dir) {
    int v = blockIdx.x * 256 + threadIdx.x;
    if (v >= DHW) return;

    const float4* src = dir ? g_neuB : g_neuA;
    float4*       dst = dir ? g_neuA : g_neuB;
    const ulonglong2* s2 = reinterpret_cast<const ulonglong2*>(src);

    int x = v % WW;
    int t = v / WW;
    int y = t % HH;
    int z = t / HH;

    const float4* wp = syn4 + (size_t)v * 54;   // 216 weights = 54 float4

    unsigned long long a0 = 0ull, a1 = 0ull;    // (b0,b1), (b2,b3) accumulators

#pragma unroll
    for (int q = 0; q < 54; ++q) {
        float4 w4 = wp[q];
#pragma unroll
        for (int u = 0; u < 4; ++u) {
            const int l  = q * 4 + u;
            const int dz = l / 36;
            const int dy = (l / 6) % 6;
            const int dx = l % 6;
            float w = (u == 0) ? w4.x : (u == 1) ? w4.y : (u == 2) ? w4.z : w4.w;
            bool ok = ((unsigned)(z + dz - 3) < (unsigned)DD) &
                      ((unsigned)(y + dy - 3) < (unsigned)HH) &
                      ((unsigned)(x + dx - 3) < (unsigned)WW);
            if (ok) {
                const int off = ((dz - 3) * HH + (dy - 3)) * WW + (dx - 3); // compile-time const
                ulonglong2 n = s2[v + off];
                unsigned long long wpk = pack2(w);
                ffma2(a0, n.x, wpk);
                ffma2(a1, n.y, wpk);
            }
        }
    }

    float2 r0 = unpack2(a0);
    float2 r1 = unpack2(a1);
    float4 o;
    o.x = fmaxf(r0.x, 0.f) * CONVEY;
    o.y = fmaxf(r0.y, 0.f) * CONVEY;
    o.z = fmaxf(r1.x, 0.f) * CONVEY;
    o.w = fmaxf(r1.y, 0.f) * CONVEY;
    dst[v] = o;
}

// ---------------- kernel 3: bias-initialize accumulators (every launch!) ----------------
__global__ void __launch_bounds__(256) k_init_acc(const float* __restrict__ b1,
                                                  const float* __restrict__ b2) {
    int i = blockIdx.x * 256 + threadIdx.x;
    if (i < NB * N1) g_acc1[i] = b1[i & (N1 - 1)];
    if (i < NB * N2) g_acc2[i] = b2[i & (N2 - 1)];
}

// ---------------- kernel 4: FC1 split-K, atomics into g_acc1 ----------------
// Final neu state lives in g_neuB (5 steps starting from A).
#define KSPLIT 576
#define ROWSPB 176   // 576 * 176 == 101376 exactly
__global__ void __launch_bounds__(256) k_gemm1(const float* __restrict__ W1) {
    __shared__ float4 sx[ROWSPB];
    const int f0 = blockIdx.x * ROWSPB;

    for (int i = threadIdx.x; i < ROWSPB; i += 256) sx[i] = g_neuB[f0 + i];
    __syncthreads();

    const int j0 = threadIdx.x * 4;   // 4 consecutive output columns per thread
    float a00=0,a01=0,a02=0,a03=0;
    float a10=0,a11=0,a12=0,a13=0;
    float a20=0,a21=0,a22=0,a23=0;
    float a30=0,a31=0,a32=0,a33=0;

#pragma unroll 4
    for (int i = 0; i < ROWSPB; ++i) {
        float4 w  = *reinterpret_cast<const float4*>(W1 + (size_t)(f0 + i) * N1 + j0);
        float4 xv = sx[i];
        a00 += xv.x * w.x; a01 += xv.x * w.y; a02 += xv.x * w.z; a03 += xv.x * w.w;
        a10 += xv.y * w.x; a11 += xv.y * w.y; a12 += xv.y * w.z; a13 += xv.y * w.w;
        a20 += xv.z * w.x; a21 += xv.z * w.y; a22 += xv.z * w.z; a23 += xv.z * w.w;
        a30 += xv.w * w.x; a31 += xv.w * w.y; a32 += xv.w * w.z; a33 += xv.w * w.w;
    }

    atomicAdd(&g_acc1[0 * N1 + j0 + 0], a00); atomicAdd(&g_acc1[0 * N1 + j0 + 1], a01);
    atomicAdd(&g_acc1[0 * N1 + j0 + 2], a02); atomicAdd(&g_acc1[0 * N1 + j0 + 3], a03);
    atomicAdd(&g_acc1[1 * N1 + j0 + 0], a10); atomicAdd(&g_acc1[1 * N1 + j0 + 1], a11);
    atomicAdd(&g_acc1[1 * N1 + j0 + 2], a12); atomicAdd(&g_acc1[1 * N1 + j0 + 3], a13);
    atomicAdd(&g_acc1[2 * N1 + j0 + 0], a20); atomicAdd(&g_acc1[2 * N1 + j0 + 1], a21);
    atomicAdd(&g_acc1[2 * N1 + j0 + 2], a22); atomicAdd(&g_acc1[2 * N1 + j0 + 3], a23);
    atomicAdd(&g_acc1[3 * N1 + j0 + 0], a30); atomicAdd(&g_acc1[3 * N1 + j0 + 1], a31);
    atomicAdd(&g_acc1[3 * N1 + j0 + 2], a32); atomicAdd(&g_acc1[3 * N1 + j0 + 3], a33);
}

// ---------------- kernel 5: FC2 (relu(acc1) @ W2), atomics into g_acc2 ----------------
__global__ void __launch_bounds__(128) k_gemm2(const float* __restrict__ W2) {
    const int t     = threadIdx.x;      // output column 0..127
    const int jbase = blockIdx.x * 64;  // 16 blocks cover j = 0..1023
    float acc0 = 0, acc1 = 0, acc2 = 0, acc3 = 0;
#pragma unroll 4
    for (int j = 0; j < 64; ++j) {
        int jj  = jbase + j;
        float w = W2[(size_t)jj * N2 + t];
        acc0 += fmaxf(g_acc1[0 * N1 + jj], 0.f) * w;
        acc1 += fmaxf(g_acc1[1 * N1 + jj], 0.f) * w;
        acc2 += fmaxf(g_acc1[2 * N1 + jj], 0.f) * w;
        acc3 += fmaxf(g_acc1[3 * N1 + jj], 0.f) * w;
    }
    atomicAdd(&g_acc2[0 * N2 + t], acc0);
    atomicAdd(&g_acc2[1 * N2 + t], acc1);
    atomicAdd(&g_acc2[2 * N2 + t], acc2);
    atomicAdd(&g_acc2[3 * N2 + t], acc3);
}

// ---------------- kernel 6: FC3 -> output logits ----------------
__global__ void __launch_bounds__(64) k_fc3(const float* __restrict__ W3,
                                            const float* __restrict__ b3,
                                            float* __restrict__ out) {
    int t = threadIdx.x;
    if (t >= NB * N3) return;
    int b = t / N3, o = t % N3;
    float s = b3[o];
#pragma unroll 8
    for (int k = 0; k < N2; ++k)
        s += fmaxf(g_acc2[b * N2 + k], 0.f) * W3[k * N3 + o];
    out[b * N3 + o] = s;
}

// ---------------- launch ----------------
extern "C" void kernel_launch(void* const* d_in, const int* in_sizes, int n_in,
                              void* d_out, int out_size) {
    const float* vin   = (const float*)d_in[0];
    const float* frame = (const float*)d_in[1];
    const float* syn   = (const float*)d_in[2];
    const float* W1    = (const float*)d_in[3];
    const float* b1    = (const float*)d_in[4];
    const float* W2    = (const float*)d_in[5];
    const float* b2    = (const float*)d_in[6];
    const float* W3    = (const float*)d_in[7];
    const float* b3    = (const float*)d_in[8];
    float* out = (float*)d_out;

    const int NBLK = DHW / 256;  // 396, exact

    k_init_neu<<<NBLK, 256>>>(vin, frame);

    const float4* syn4 = (const float4*)syn;
    k_step<<<NBLK, 256>>>(syn4, 0);   // A -> B
    k_step<<<NBLK, 256>>>(syn4, 1);   // B -> A
    k_step<<<NBLK, 256>>>(syn4, 0);   // A -> B
    k_step<<<NBLK, 256>>>(syn4, 1);   // B -> A
    k_step<<<NBLK, 256>>>(syn4, 0);   // A -> B  (final state in g_neuB)

    k_init_acc<<<18, 256>>>(b1, b2);
    k_gemm1<<<KSPLIT, 256>>>(W1);
    k_gemm2<<<16, 128>>>(W2);
    k_fc3<<<1, 64>>>(W3, b3, out);
}

// round 2
// speedup vs baseline: 1.1925x; 1.1925x over previous
#include <cuda_runtime.h>
#include <cstdint>

// ---------------- problem constants ----------------
#define DD   44          // DESIZE
#define HH   48
#define WW   48
#define DHW  (DD*HH*WW)  // 101376 = FLAT
#define NB   4           // batch
#define N1   1024
#define N2   128
#define N3   10
#define NT   216         // 6*6*6 taps
#define CONVEY 0.9f

// tile geometry for k_step
#define TX 16
#define TY 16
#define HX 21            // TX + 5
#define HY 21            // TY + 5
#define HZ 6
#define TILE_ELEMS (HZ*HY*HX)   // 2646
#define NSTEPBLK (3*3*DD)       // 396 step blocks of 256 voxels

// ---------------- device scratch (no allocation allowed) ----------------
__device__ float4 g_neuA[DHW];           // batch-packed neuron state, ping
__device__ float4 g_neuB[DHW];           // pong
__device__ float  g_synT[(size_t)NT * DHW]; // transposed+block-permuted synapse (87.6MB)
__device__ float  g_acc1[NB * N1];
__device__ float  g_acc2[NB * N2];

// ---------------- packed fp32x2 helpers (Blackwell) ----------------
__device__ __forceinline__ unsigned long long pack2(float w) {
    unsigned long long r;
    asm("mov.b64 %0, {%1, %1};" : "=l"(r) : "f"(w));
    return r;
}
__device__ __forceinline__ void ffma2(unsigned long long& acc,
                                      unsigned long long a,
                                      unsigned long long b) {
    asm("fma.rn.f32x2 %0, %1, %2, %0;" : "+l"(acc) : "l"(a), "l"(b));
}
__device__ __forceinline__ float2 unpack2(unsigned long long v) {
    float2 f;
    asm("mov.b64 {%0, %1}, %2;" : "=f"(f.x), "=f"(f.y) : "l"(v));
    return f;
}

// ---------------- kernel 1: neu = vinput + frame, batch-packed ----------------
__global__ void __launch_bounds__(256) k_init_neu(const float* __restrict__ vin,
                                                  const float* __restrict__ frame) {
    int v = blockIdx.x * 256 + threadIdx.x;
    if (v >= DHW) return;
    float f = frame[v];
    float4 o;
    o.x = vin[0 * DHW + v] + f;
    o.y = vin[1 * DHW + v] + f;
    o.z = vin[2 * DHW + v] + f;
    o.w = vin[3 * DHW + v] + f;
    g_neuA[v] = o;
}

// ---------------- kernel 1b: transpose synapse [vox][tap] -> [tap][permvox] ----
// permvox order: step-block linear id * 256 + (ty*16+tx), so k_step weight loads
// are perfectly coalesced (256 consecutive floats per block per tap).
// Each transpose block handles 32 voxels (one warp-chunk of a step block):
// those 32 voxels are 2 x-rows of 16 -> two contiguous 3456-float gmem chunks.
__global__ void __launch_bounds__(256) k_transpose(const float* __restrict__ syn) {
    __shared__ float sm[32 * 217];
    const int b  = blockIdx.x;       // 0..3167
    const int sb = b >> 3;           // step block 0..395
    const int w  = b & 7;            // warp-chunk 0..7
    const int bx = sb % 3;
    const int tq = sb / 3;
    const int by = tq % 3;
    const int z  = tq / 3;
    const int x0 = bx * TX, y0 = by * TY;
    const int t  = threadIdx.x;

    const size_t base0 = ((size_t)z * (HH*WW) + (size_t)(y0 + 2*w    ) * WW + x0) * NT;
    const size_t base1 = ((size_t)z * (HH*WW) + (size_t)(y0 + 2*w + 1) * WW + x0) * NT;

#pragma unroll
    for (int i = 0; i < 27; ++i) {          // 27*256 = 6912 = 32*216
        int idx    = i * 256 + t;
        int chunk  = idx / 3456;
        int within = idx - chunk * 3456;
        int vl     = within / NT;            // 0..15
        int tap    = within - vl * NT;
        float val  = syn[(chunk ? base1 : base0) + within];
        sm[(chunk * 16 + vl) * 217 + tap] = val;
    }
    __syncthreads();

    const int lane = t & 31;
    const int jrow = t >> 5;                 // 0..7
    const size_t obase = (size_t)sb * 256 + w * 32 + lane;
#pragma unroll
    for (int jj = jrow; jj < NT; jj += 8)
        g_synT[(size_t)jj * DHW + obase] = sm[lane * 217 + jj];
}

// ---------------- kernel 2: one locally-connected step (tiled) ----------------
// dir = 0: A -> B, dir = 1: B -> A
__global__ void __launch_bounds__(256) k_step(int dir) {
    __shared__ float4 tile[TILE_ELEMS];      // 42336 B, zero-padded halo

    const int sb = blockIdx.x;               // 0..395
    const int bx = sb % 3;
    const int tq = sb / 3;
    const int by = tq % 3;
    const int z  = tq / 3;
    const int x0 = bx * TX, y0 = by * TY;
    const int t  = threadIdx.x;
    const int tx = t & 15, ty = t >> 4;

    const float4* __restrict__ src = dir ? g_neuB : g_neuA;
    float4*       __restrict__ dst = dir ? g_neuA : g_neuB;

    // load halo tile (zeros outside the volume -> no predication in tap loop)
#pragma unroll
    for (int i = 0; i < 11; ++i) {
        int idx = i * 256 + t;
        if (idx < TILE_ELEMS) {
            int lx = idx % HX;
            int r  = idx / HX;
            int ly = r % HY;
            int lz = r / HY;
            int gx = x0 + lx - 3, gy = y0 + ly - 3, gz = z + lz - 3;
            float4 v = make_float4(0.f, 0.f, 0.f, 0.f);
            if ((unsigned)gx < (unsigned)WW && (unsigned)gy < (unsigned)HH &&
                (unsigned)gz < (unsigned)DD)
                v = src[((size_t)gz * HH + gy) * WW + gx];
            tile[idx] = v;
        }
    }
    __syncthreads();

    const float* __restrict__ wp = g_synT + (size_t)sb * 256 + t;  // +l*DHW per tap
    const ulonglong2* tl2 = reinterpret_cast<const ulonglong2*>(tile);

    unsigned long long a0 = 0ull, a1 = 0ull;

#pragma unroll
    for (int l = 0; l < NT; ++l) {
        const int dz = l / 36;
        const int dy = (l / 6) % 6;
        const int dx = l % 6;
        float w = wp[(size_t)l * DHW];                 // coalesced 128B/warp
        ulonglong2 n = tl2[(dz * HY + ty + dy) * HX + tx + dx];
        unsigned long long w2 = pack2(w);
        ffma2(a0, n.x, w2);
        ffma2(a1, n.y, w2);
    }

    float2 r0 = unpack2(a0);
    float2 r1 = unpack2(a1);
    float4 o;
    o.x = fmaxf(r0.x, 0.f) * CONVEY;
    o.y = fmaxf(r0.y, 0.f) * CONVEY;
    o.z = fmaxf(r1.x, 0.f) * CONVEY;
    o.w = fmaxf(r1.y, 0.f) * CONVEY;
    dst[((size_t)z * HH + (y0 + ty)) * WW + (x0 + tx)] = o;
}

// ---------------- kernel 3: bias-initialize accumulators (every launch!) ------
__global__ void __launch_bounds__(256) k_init_acc(const float* __restrict__ b1,
                                                  const float* __restrict__ b2) {
    int i = blockIdx.x * 256 + threadIdx.x;
    if (i < NB * N1) g_acc1[i] = b1[i & (N1 - 1)];
    if (i < NB * N2) g_acc2[i] = b2[i & (N2 - 1)];
}

// ---------------- kernel 4: FC1 split-K, atomics into g_acc1 ------------------
// Final neu state lives in g_neuB (5 steps starting from A).
#define KSPLIT 576
#define ROWSPB 176   // 576 * 176 == 101376 exactly
__global__ void __launch_bounds__(256) k_gemm1(const float* __restrict__ W1) {
    __shared__ float4 sx[ROWSPB];
    const int f0 = blockIdx.x * ROWSPB;

    for (int i = threadIdx.x; i < ROWSPB; i += 256) sx[i] = g_neuB[f0 + i];
    __syncthreads();

    const int j0 = threadIdx.x * 4;   // 4 consecutive output columns per thread
    float a00=0,a01=0,a02=0,a03=0;
    float a10=0,a11=0,a12=0,a13=0;
    float a20=0,a21=0,a22=0,a23=0;
    float a30=0,a31=0,a32=0,a33=0;

#pragma unroll 4
    for (int i = 0; i < ROWSPB; ++i) {
        float4 w  = *reinterpret_cast<const float4*>(W1 + (size_t)(f0 + i) * N1 + j0);
        float4 xv = sx[i];
        a00 += xv.x * w.x; a01 += xv.x * w.y; a02 += xv.x * w.z; a03 += xv.x * w.w;
        a10 += xv.y * w.x; a11 += xv.y * w.y; a12 += xv.y * w.z; a13 += xv.y * w.w;
        a20 += xv.z * w.x; a21 += xv.z * w.y; a22 += xv.z * w.z; a23 += xv.z * w.w;
        a30 += xv.w * w.x; a31 += xv.w * w.y; a32 += xv.w * w.z; a33 += xv.w * w.w;
    }

    atomicAdd(&g_acc1[0 * N1 + j0 + 0], a00); atomicAdd(&g_acc1[0 * N1 + j0 + 1], a01);
    atomicAdd(&g_acc1[0 * N1 + j0 + 2], a02); atomicAdd(&g_acc1[0 * N1 + j0 + 3], a03);
    atomicAdd(&g_acc1[1 * N1 + j0 + 0], a10); atomicAdd(&g_acc1[1 * N1 + j0 + 1], a11);
    atomicAdd(&g_acc1[1 * N1 + j0 + 2], a12); atomicAdd(&g_acc1[1 * N1 + j0 + 3], a13);
    atomicAdd(&g_acc1[2 * N1 + j0 + 0], a20); atomicAdd(&g_acc1[2 * N1 + j0 + 1], a21);
    atomicAdd(&g_acc1[2 * N1 + j0 + 2], a22); atomicAdd(&g_acc1[2 * N1 + j0 + 3], a23);
    atomicAdd(&g_acc1[3 * N1 + j0 + 0], a30); atomicAdd(&g_acc1[3 * N1 + j0 + 1], a31);
    atomicAdd(&g_acc1[3 * N1 + j0 + 2], a32); atomicAdd(&g_acc1[3 * N1 + j0 + 3], a33);
}

// ---------------- kernel 5: FC2 (relu(acc1) @ W2), atomics into g_acc2 --------
__global__ void __launch_bounds__(128) k_gemm2(const float* __restrict__ W2) {
    const int t     = threadIdx.x;      // output column 0..127
    const int jbase = blockIdx.x * 64;  // 16 blocks cover j = 0..1023
    float acc0 = 0, acc1 = 0, acc2 = 0, acc3 = 0;
#pragma unroll 4
    for (int j = 0; j < 64; ++j) {
        int jj  = jbase + j;
        float w = W2[(size_t)jj * N2 + t];
        acc0 += fmaxf(g_acc1[0 * N1 + jj], 0.f) * w;
        acc1 += fmaxf(g_acc1[1 * N1 + jj], 0.f) * w;
        acc2 += fmaxf(g_acc1[2 * N1 + jj], 0.f) * w;
        acc3 += fmaxf(g_acc1[3 * N1 + jj], 0.f) * w;
    }
    atomicAdd(&g_acc2[0 * N2 + t], acc0);
    atomicAdd(&g_acc2[1 * N2 + t], acc1);
    atomicAdd(&g_acc2[2 * N2 + t], acc2);
    atomicAdd(&g_acc2[3 * N2 + t], acc3);
}

// ---------------- kernel 6: FC3 -> output logits ----------------
__global__ void __launch_bounds__(64) k_fc3(const float* __restrict__ W3,
                                            const float* __restrict__ b3,
                                            float* __restrict__ out) {
    int t = threadIdx.x;
    if (t >= NB * N3) return;
    int b = t / N3, o = t % N3;
    float s = b3[o];
#pragma unroll 8
    for (int k = 0; k < N2; ++k)
        s += fmaxf(g_acc2[b * N2 + k], 0.f) * W3[k * N3 + o];
    out[b * N3 + o] = s;
}

// ---------------- launch ----------------
extern "C" void kernel_launch(void* const* d_in, const int* in_sizes, int n_in,
                              void* d_out, int out_size) {
    const float* vin   = (const float*)d_in[0];
    const float* frame = (const float*)d_in[1];
    const float* syn   = (const float*)d_in[2];
    const float* W1    = (const float*)d_in[3];
    const float* b1    = (const float*)d_in[4];
    const float* W2    = (const float*)d_in[5];
    const float* b2    = (const float*)d_in[6];
    const float* W3    = (const float*)d_in[7];
    const float* b3    = (const float*)d_in[8];
    float* out = (float*)d_out;

    k_init_neu<<<DHW / 256, 256>>>(vin, frame);
    k_transpose<<<NSTEPBLK * 8, 256>>>(syn);

    k_step<<<NSTEPBLK, 256>>>(0);   // A -> B
    k_step<<<NSTEPBLK, 256>>>(1);   // B -> A
    k_step<<<NSTEPBLK, 256>>>(0);   // A -> B
    k_step<<<NSTEPBLK, 256>>>(1);   // B -> A
    k_step<<<NSTEPBLK, 256>>>(0);   // A -> B  (final state in g_neuB)

    k_init_acc<<<18, 256>>>(b1, b2);
    k_gemm1<<<KSPLIT, 256>>>(W1);
    k_gemm2<<<16, 128>>>(W2);
    k_fc3<<<1, 64>>>(W3, b3, out);
}

// round 3
// speedup vs baseline: 1.4500x; 1.2159x over previous
#include <cuda_runtime.h>
#include <cuda_fp16.h>
#include <cstdint>

// ---------------- problem constants ----------------
#define DD   44          // DESIZE
#define HH   48
#define WW   48
#define DHW  (DD*HH*WW)  // 101376 = FLAT
#define NB   4           // batch
#define N1   1024
#define N2   128
#define N3   10
#define NT   216         // 6*6*6 taps
#define NP   108         // tap pairs
#define CONVEY 0.9f

// tile geometry for k_step
#define TX 16
#define TY 16
#define HX 21            // TX + 5
#define HY 21
#define HZ 6
#define HXE 11           // even window positions 0,2,..,20
#define HXO 10           // odd positions 1,3,..,19
#define TILE_ELEMS (HZ*HY*HX)   // 2646
#define NSTEPBLK (3*3*DD)       // 396 blocks, 256 voxels each

// ---------------- device scratch (no allocation allowed) ----------------
__device__ float4 g_neuA[DHW];
__device__ float4 g_neuB[DHW];
__device__ __align__(16) __half2 g_synTh[(size_t)NP * DHW]; // [pair][permvox] fp16 (43.8MB)
__device__ float  g_acc1[NB * N1];
__device__ float  g_acc2[NB * N2];

// ---------------- packed fp32x2 helpers (Blackwell) ----------------
__device__ __forceinline__ unsigned long long pack2(float w) {
    unsigned long long r;
    asm("mov.b64 %0, {%1, %1};" : "=l"(r) : "f"(w));
    return r;
}
__device__ __forceinline__ void ffma2(unsigned long long& acc,
                                      unsigned long long a,
                                      unsigned long long b) {
    asm("fma.rn.f32x2 %0, %1, %2, %0;" : "+l"(acc) : "l"(a), "l"(b));
}
__device__ __forceinline__ float2 unpack2(unsigned long long v) {
    float2 f;
    asm("mov.b64 {%0, %1}, %2;" : "=f"(f.x), "=f"(f.y) : "l"(v));
    return f;
}

// ---------------- kernel 1: neu = vinput + frame, batch-packed ----------------
__global__ void __launch_bounds__(256) k_init_neu(const float* __restrict__ vin,
                                                  const float* __restrict__ frame) {
    int v = blockIdx.x * 256 + threadIdx.x;
    if (v >= DHW) return;
    float f = frame[v];
    float4 o;
    o.x = vin[0 * DHW + v] + f;
    o.y = vin[1 * DHW + v] + f;
    o.z = vin[2 * DHW + v] + f;
    o.w = vin[3 * DHW + v] + f;
    g_neuA[v] = o;
}

// ---------------- kernel 1b: transpose synapse [vox][tap] -> fp16 [pair][permvox]
// permvox: step-block id * 256 + (ty*16+tx). Each transpose block handles one
// warp-chunk (32 voxels = 2 contiguous x-rows of 16) of a step block.
__global__ void __launch_bounds__(256) k_transpose(const float* __restrict__ syn) {
    __shared__ float sm[32 * 217];
    const int b  = blockIdx.x;       // 0..3167
    const int sb = b >> 3;           // step block 0..395
    const int w  = b & 7;            // warp-chunk 0..7
    const int bx = sb % 3;
    const int tq = sb / 3;
    const int by = tq % 3;
    const int z  = tq / 3;
    const int x0 = bx * TX, y0 = by * TY;
    const int t  = threadIdx.x;

    const size_t base0 = ((size_t)z * (HH*WW) + (size_t)(y0 + 2*w    ) * WW + x0) * NT;
    const size_t base1 = ((size_t)z * (HH*WW) + (size_t)(y0 + 2*w + 1) * WW + x0) * NT;

#pragma unroll
    for (int i = 0; i < 27; ++i) {          // 27*256 = 6912 = 32*216
        int idx    = i * 256 + t;
        int chunk  = idx / 3456;
        int within = idx - chunk * 3456;
        int vl     = within / NT;            // 0..15
        int tap    = within - vl * NT;
        float val  = syn[(chunk ? base1 : base0) + within];
        sm[(chunk * 16 + vl) * 217 + tap] = val;
    }
    __syncthreads();

    const int lane = t & 31;
    const int prow = t >> 5;                 // 0..7
    const size_t obase = (size_t)sb * 256 + w * 32 + lane;
#pragma unroll
    for (int p = prow; p < NP; p += 8) {
        float w0 = sm[lane * 217 + 2 * p];
        float w1 = sm[lane * 217 + 2 * p + 1];
        g_synTh[(size_t)p * DHW + obase] = __floats2half2_rn(w0, w1);
    }
}

// ---------------- kernel 2: one locally-connected step (tiled, x-paired) ------
// 128 threads; thread handles voxels x = x0+2*txp and x0+2*txp+1 at row ty.
// dir = 0: A -> B, dir = 1: B -> A
__global__ void __launch_bounds__(128) k_step(int dir) {
    __shared__ float4 tileE[HZ * HY * HXE];   // even local-x positions
    __shared__ float4 tileO[HZ * HY * HXO];   // odd  local-x positions

    const int sb = blockIdx.x;               // 0..395
    const int bx = sb % 3;
    const int tq = sb / 3;
    const int by = tq % 3;
    const int z  = tq / 3;
    const int x0 = bx * TX, y0 = by * TY;
    const int t  = threadIdx.x;
    const int txp = t & 7;                   // x-pair 0..7
    const int ty  = t >> 3;                  // 0..15

    const float4* __restrict__ src = dir ? g_neuB : g_neuA;
    float4*       __restrict__ dst = dir ? g_neuA : g_neuB;

    // load halo tile (zeros outside the volume)
#pragma unroll
    for (int i = 0; i < 21; ++i) {
        int idx = i * 128 + t;
        if (idx < TILE_ELEMS) {
            int lp = idx % HX;
            int r  = idx / HX;
            int ly = r % HY;
            int lz = r / HY;
            int gx = x0 + lp - 3, gy = y0 + ly - 3, gz = z + lz - 3;
            float4 v = make_float4(0.f, 0.f, 0.f, 0.f);
            if ((unsigned)gx < (unsigned)WW && (unsigned)gy < (unsigned)HH &&
                (unsigned)gz < (unsigned)DD)
                v = src[((size_t)gz * HH + gy) * WW + gx];
            if (lp & 1) tileO[(lz * HY + ly) * HXO + (lp >> 1)] = v;
            else        tileE[(lz * HY + ly) * HXE + (lp >> 1)] = v;
        }
    }
    __syncthreads();

    const int v0 = ty * 16 + 2 * txp;
    const char* wbase = reinterpret_cast<const char*>(g_synTh + ((size_t)sb * 256 + v0));

    const ulonglong2* tE = reinterpret_cast<const ulonglong2*>(tileE);
    const ulonglong2* tO = reinterpret_cast<const ulonglong2*>(tileO);

    unsigned long long a0 = 0ull, a1 = 0ull;  // voxel v0: (b0,b1), (b2,b3)
    unsigned long long c0 = 0ull, c1 = 0ull;  // voxel v0+1

#pragma unroll
    for (int dz = 0; dz < 6; ++dz) {
#pragma unroll
        for (int dy = 0; dy < 6; ++dy) {
            const int row = (dz * HY + ty + dy);
            const ulonglong2* rE = tE + row * HXE + txp;
            const ulonglong2* rO = tO + row * HXO + txp;
            ulonglong2 n0 = rE[0];   // window pos 2txp+0
            ulonglong2 n1 = rO[0];   // +1
            ulonglong2 n2 = rE[1];   // +2
            ulonglong2 n3 = rO[1];   // +3
            ulonglong2 n4 = rE[2];   // +4
            ulonglong2 n5 = rO[2];   // +5
            ulonglong2 n6 = rE[3];   // +6
            const size_t pbase = (size_t)(dz * 18 + dy * 3) * DHW;

#pragma unroll
            for (int q = 0; q < 3; ++q) {
                uint2 u = *reinterpret_cast<const uint2*>(wbase + (pbase + (size_t)q * DHW) * 4);
                float2 fa = __half22float2(*reinterpret_cast<__half2*>(&u.x)); // v0: taps 2q,2q+1
                float2 fb = __half22float2(*reinterpret_cast<__half2*>(&u.y)); // v1: taps 2q,2q+1
                unsigned long long wax = pack2(fa.x), way = pack2(fa.y);
                unsigned long long wbx = pack2(fb.x), wby = pack2(fb.y);
                const ulonglong2* m0 = (q == 0) ? &n0 : (q == 1) ? &n2 : &n4; // v0 tap dx=2q
                const ulonglong2* m1 = (q == 0) ? &n1 : (q == 1) ? &n3 : &n5; // shared middle
                const ulonglong2* m2 = (q == 0) ? &n2 : (q == 1) ? &n4 : &n6; // v1 tap dx=2q+1
                ffma2(a0, m0->x, wax); ffma2(a1, m0->y, wax);
                ffma2(a0, m1->x, way); ffma2(a1, m1->y, way);
                ffma2(c0, m1->x, wbx); ffma2(c1, m1->y, wbx);
                ffma2(c0, m2->x, wby); ffma2(c1, m2->y, wby);
            }
        }
    }

    float2 r0 = unpack2(a0), r1 = unpack2(a1);
    float2 s0 = unpack2(c0), s1 = unpack2(c1);
    float4 oA, oB;
    oA.x = fmaxf(r0.x, 0.f) * CONVEY;
    oA.y = fmaxf(r0.y, 0.f) * CONVEY;
    oA.z = fmaxf(r1.x, 0.f) * CONVEY;
    oA.w = fmaxf(r1.y, 0.f) * CONVEY;
    oB.x = fmaxf(s0.x, 0.f) * CONVEY;
    oB.y = fmaxf(s0.y, 0.f) * CONVEY;
    oB.z = fmaxf(s1.x, 0.f) * CONVEY;
    oB.w = fmaxf(s1.y, 0.f) * CONVEY;
    size_t obase = ((size_t)z * HH + (y0 + ty)) * WW + (x0 + 2 * txp);
    dst[obase]     = oA;
    dst[obase + 1] = oB;
}

// ---------------- kernel 3: bias-initialize accumulators (every launch!) ------
__global__ void __launch_bounds__(256) k_init_acc(const float* __restrict__ b1,
                                                  const float* __restrict__ b2) {
    int i = blockIdx.x * 256 + threadIdx.x;
    if (i < NB * N1) g_acc1[i] = b1[i & (N1 - 1)];
    if (i < NB * N2) g_acc2[i] = b2[i & (N2 - 1)];
}

// ---------------- kernel 4: FC1 split-K, atomics into g_acc1 ------------------
#define KSPLIT 576
#define ROWSPB 176   // 576 * 176 == 101376 exactly
__global__ void __launch_bounds__(256) k_gemm1(const float* __restrict__ W1) {
    __shared__ float4 sx[ROWSPB];
    const int f0 = blockIdx.x * ROWSPB;

    for (int i = threadIdx.x; i < ROWSPB; i += 256) sx[i] = g_neuB[f0 + i];
    __syncthreads();

    const int j0 = threadIdx.x * 4;
    float a00=0,a01=0,a02=0,a03=0;
    float a10=0,a11=0,a12=0,a13=0;
    float a20=0,a21=0,a22=0,a23=0;
    float a30=0,a31=0,a32=0,a33=0;

#pragma unroll 8
    for (int i = 0; i < ROWSPB; ++i) {
        float4 w  = *reinterpret_cast<const float4*>(W1 + (size_t)(f0 + i) * N1 + j0);
        float4 xv = sx[i];
        a00 += xv.x * w.x; a01 += xv.x * w.y; a02 += xv.x * w.z; a03 += xv.x * w.w;
        a10 += xv.y * w.x; a11 += xv.y * w.y; a12 += xv.y * w.z; a13 += xv.y * w.w;
        a20 += xv.z * w.x; a21 += xv.z * w.y; a22 += xv.z * w.z; a23 += xv.z * w.w;
        a30 += xv.w * w.x; a31 += xv.w * w.y; a32 += xv.w * w.z; a33 += xv.w * w.w;
    }

    atomicAdd(&g_acc1[0 * N1 + j0 + 0], a00); atomicAdd(&g_acc1[0 * N1 + j0 + 1], a01);
    atomicAdd(&g_acc1[0 * N1 + j0 + 2], a02); atomicAdd(&g_acc1[0 * N1 + j0 + 3], a03);
    atomicAdd(&g_acc1[1 * N1 + j0 + 0], a10); atomicAdd(&g_acc1[1 * N1 + j0 + 1], a11);
    atomicAdd(&g_acc1[1 * N1 + j0 + 2], a12); atomicAdd(&g_acc1[1 * N1 + j0 + 3], a13);
    atomicAdd(&g_acc1[2 * N1 + j0 + 0], a20); atomicAdd(&g_acc1[2 * N1 + j0 + 1], a21);
    atomicAdd(&g_acc1[2 * N1 + j0 + 2], a22); atomicAdd(&g_acc1[2 * N1 + j0 + 3], a23);
    atomicAdd(&g_acc1[3 * N1 + j0 + 0], a30); atomicAdd(&g_acc1[3 * N1 + j0 + 1], a31);
    atomicAdd(&g_acc1[3 * N1 + j0 + 2], a32); atomicAdd(&g_acc1[3 * N1 + j0 + 3], a33);
}

// ---------------- kernel 5: FC2 (relu(acc1) @ W2), atomics into g_acc2 --------
__global__ void __launch_bounds__(128) k_gemm2(const float* __restrict__ W2) {
    const int t     = threadIdx.x;
    const int jbase = blockIdx.x * 64;
    float acc0 = 0, acc1 = 0, acc2 = 0, acc3 = 0;
#pragma unroll 4
    for (int j = 0; j < 64; ++j) {
        int jj  = jbase + j;
        float w = W2[(size_t)jj * N2 + t];
        acc0 += fmaxf(g_acc1[0 * N1 + jj], 0.f) * w;
        acc1 += fmaxf(g_acc1[1 * N1 + jj], 0.f) * w;
        acc2 += fmaxf(g_acc1[2 * N1 + jj], 0.f) * w;
        acc3 += fmaxf(g_acc1[3 * N1 + jj], 0.f) * w;
    }
    atomicAdd(&g_acc2[0 * N2 + t], acc0);
    atomicAdd(&g_acc2[1 * N2 + t], acc1);
    atomicAdd(&g_acc2[2 * N2 + t], acc2);
    atomicAdd(&g_acc2[3 * N2 + t], acc3);
}

// ---------------- kernel 6: FC3 -> output logits ----------------
__global__ void __launch_bounds__(64) k_fc3(const float* __restrict__ W3,
                                            const float* __restrict__ b3,
                                            float* __restrict__ out) {
    int t = threadIdx.x;
    if (t >= NB * N3) return;
    int b = t / N3, o = t % N3;
    float s = b3[o];
#pragma unroll 8
    for (int k = 0; k < N2; ++k)
        s += fmaxf(g_acc2[b * N2 + k], 0.f) * W3[k * N3 + o];
    out[b * N3 + o] = s;
}

// ---------------- launch ----------------
extern "C" void kernel_launch(void* const* d_in, const int* in_sizes, int n_in,
                              void* d_out, int out_size) {
    const float* vin   = (const float*)d_in[0];
    const float* frame = (const float*)d_in[1];
    const float* syn   = (const float*)d_in[2];
    const float* W1    = (const float*)d_in[3];
    const float* b1    = (const float*)d_in[4];
    const float* W2    = (const float*)d_in[5];
    const float* b2    = (const float*)d_in[6];
    const float* W3    = (const float*)d_in[7];
    const float* b3    = (const float*)d_in[8];
    float* out = (float*)d_out;

    k_init_neu<<<DHW / 256, 256>>>(vin, frame);
    k_transpose<<<NSTEPBLK * 8, 256>>>(syn);

    k_step<<<NSTEPBLK, 128>>>(0);   // A -> B
    k_step<<<NSTEPBLK, 128>>>(1);   // B -> A
    k_step<<<NSTEPBLK, 128>>>(0);   // A -> B
    k_step<<<NSTEPBLK, 128>>>(1);   // B -> A
    k_step<<<NSTEPBLK, 128>>>(0);   // A -> B  (final state in g_neuB)

    k_init_acc<<<18, 256>>>(b1, b2);
    k_gemm1<<<KSPLIT, 256>>>(W1);
    k_gemm2<<<16, 128>>>(W2);
    k_fc3<<<1, 64>>>(W3, b3, out);
}